// round 17
// baseline (speedup 1.0000x reference)
#include <cuda_runtime.h>

// out[b,u] = prod_f(in[b,f]*w[f,u]) + bias[u] = P[b]*W[u] + bias[u]
// B=32768, F=32, U=256.
//
// Final form. Nine design variants (store mechanism STG.128/.256/.cs/TMA-bulk,
// traffic 46-70MB, occupancy 36-80%, grids 296-4096, MLP 1-2, FFMA/FFMA2) all
// land at 10.7-11.0us total: the kernel is pinned at the SM store-datapath
// floor for the mandatory 32MB fp32 output (~3.3TB/s effective, identical for
// generic-proxy and async-proxy stores). This is the best-measured structure:
// one launch, one wave, warp-autonomous after a single barrier.
static constexpr int Bn = 32768;
static constexpr int Fn = 32;
static constexpr int Un = 256;

static constexpr int THREADS       = 256;               // 8 warps
static constexpr int ROWS_PER_WARP = 8;                 // 2 independent LDG.128/lane
static constexpr int ROWS_PER_BLK  = ROWS_PER_WARP * 8; // 64
static constexpr int GRID          = Bn / ROWS_PER_BLK; // 512 -> one wave

__global__ __launch_bounds__(THREADS)
void fused_kernel(const float* __restrict__ in,
                  const float* __restrict__ w,
                  const float* __restrict__ bias,
                  float* __restrict__ out) {
    __shared__ float sW[Un];

    const int t    = threadIdx.x;
    const int lane = t & 31;
    const int warp = t >> 5;

    // ---- issue BOTH input loads first (MLP=2): 8 rows * 32 f = 64 float4 ----
    // lane l: v0 covers rows 0..3 (float4 idx l), v1 rows 4..7 (idx l+32)
    const long long rowbase = (long long)blockIdx.x * ROWS_PER_BLK
                            + (long long)warp * ROWS_PER_WARP;
    const float4* in4 = reinterpret_cast<const float4*>(in + rowbase * Fn);
    const float4 v0 = in4[lane];
    const float4 v1 = in4[lane + 32];

    // ---- one-time W phase: thread t owns column t; 4 independent chains ----
    {
        float q0 = 1.0f, q1 = 1.0f, q2 = 1.0f, q3 = 1.0f;
#pragma unroll
        for (int f = 0; f < Fn; f += 4) {
            q0 *= w[(f + 0) * Un + t];
            q1 *= w[(f + 1) * Un + t];
            q2 *= w[(f + 2) * Un + t];
            q3 *= w[(f + 3) * Un + t];
        }
        sW[t] = (q0 * q1) * (q2 * q3);
    }

    // bias -> regs, independent of everything above (L2-hit after wave start)
    const float4* B4 = reinterpret_cast<const float4*>(bias);
    const float4 bv0 = B4[lane];
    const float4 bv1 = B4[lane + 32];

    __syncthreads();

    // W -> regs (lane owns float4 columns `lane` and `lane+32`)
    const float4* sW4 = reinterpret_cast<const float4*>(sW);
    const float4 wv0 = sW4[lane];
    const float4 wv1 = sW4[lane + 32];

    // ---- two interleaved row-product reductions (independent chains) ----
    float p0 = v0.x * v0.y * v0.z * v0.w;
    float p1 = v1.x * v1.y * v1.z * v1.w;
    p0 *= __shfl_xor_sync(0xffffffffu, p0, 1);
    p1 *= __shfl_xor_sync(0xffffffffu, p1, 1);
    p0 *= __shfl_xor_sync(0xffffffffu, p0, 2);
    p1 *= __shfl_xor_sync(0xffffffffu, p1, 2);
    p0 *= __shfl_xor_sync(0xffffffffu, p0, 4);
    p1 *= __shfl_xor_sync(0xffffffffu, p1, 4);
    // lanes 8r..8r+7: p0 = product of row (rowbase+r), p1 = row (rowbase+4+r)

    // ---- 16 coalesced, fully independent STG.128 per warp ----
    float4* out4 = reinterpret_cast<float4*>(out + rowbase * Un);
#pragma unroll
    for (int r = 0; r < 4; ++r) {
        const float pa = __shfl_sync(0xffffffffu, p0, r * 8);
        const float pb = __shfl_sync(0xffffffffu, p1, r * 8);
        float4 oa0, oa1, ob0, ob1;
        oa0.x = fmaf(pa, wv0.x, bv0.x);  oa0.y = fmaf(pa, wv0.y, bv0.y);
        oa0.z = fmaf(pa, wv0.z, bv0.z);  oa0.w = fmaf(pa, wv0.w, bv0.w);
        oa1.x = fmaf(pa, wv1.x, bv1.x);  oa1.y = fmaf(pa, wv1.y, bv1.y);
        oa1.z = fmaf(pa, wv1.z, bv1.z);  oa1.w = fmaf(pa, wv1.w, bv1.w);
        ob0.x = fmaf(pb, wv0.x, bv0.x);  ob0.y = fmaf(pb, wv0.y, bv0.y);
        ob0.z = fmaf(pb, wv0.z, bv0.z);  ob0.w = fmaf(pb, wv0.w, bv0.w);
        ob1.x = fmaf(pb, wv1.x, bv1.x);  ob1.y = fmaf(pb, wv1.y, bv1.y);
        ob1.z = fmaf(pb, wv1.z, bv1.z);  ob1.w = fmaf(pb, wv1.w, bv1.w);
        // row stride = 256 floats = 64 float4
        out4[(r    ) * 64 + lane]      = oa0;   // row rowbase+r
        out4[(r    ) * 64 + lane + 32] = oa1;
        out4[(r + 4) * 64 + lane]      = ob0;   // row rowbase+4+r
        out4[(r + 4) * 64 + lane + 32] = ob1;
    }
}

extern "C" void kernel_launch(void* const* d_in, const int* in_sizes, int n_in,
                              void* d_out, int out_size) {
    // metadata order: inputs [B,F], weight [F,U], weight_selector [F,U] (dead), bias [U]
    const float* in   = (const float*)d_in[0];
    const float* w    = (const float*)d_in[1];
    const float* bias = (const float*)d_in[3];
    float* out        = (float*)d_out;

    fused_kernel<<<GRID, THREADS>>>(in, w, bias, out);
}